// round 1
// baseline (speedup 1.0000x reference)
#include <cuda_runtime.h>

// HMM forward for CgpHmmCell (nCodons=2): 24 states, 17 emitting, batch=2048, T=2000.
// Sparse transition structure hardcoded; runtime softmax coefficients computed in a
// tiny setup kernel. One thread per sequence; renormalize every 16 steps.

#define T_LEN 2000
#define BATCH 2048

__device__ float g_coef[17];       // runtime softmax'd transition coefficients
__device__ float g_pi[24];         // softmax(init_kernel)
__device__ float g_Bst[64 * 20];   // emission table, layout [ctx 0..63][state 0..16, pad to 20]

// ---------------------------------------------------------------------------
// Setup kernel: compute transition coefs, pi, and the emission table.
// ---------------------------------------------------------------------------
__global__ void setup_kernel(const float* __restrict__ w,
                             const float* __restrict__ ew,
                             const float* __restrict__ ik) {
    int tid = threadIdx.x;
    if (tid == 0) {
        float w12 = w[12];
        float d1 = 1.0f - w12 * w12;          // delete skip-1
        float d2 = 1.0f - w12 * w12 * w12;    // delete skip-2
        // row 0: (0,0)=1-w0, (0,1)=w0
        {
            float v0 = 1.0f - w[0], v1 = w[0];
            float m = fmaxf(v0, v1);
            float e0 = expf(v0 - m), e1 = expf(v1 - m);
            float s = e0 + e1;
            g_coef[0] = e0 / s;   // a00
            g_coef[1] = e1 / s;   // a01
        }
        // row 3: (3,4)=w1, (3,14)=w3, (3,7)=d1, (3,10)=d2
        {
            float v0 = w[1], v1 = w[3], v2 = d1, v3 = d2;
            float m = fmaxf(fmaxf(v0, v1), fmaxf(v2, v3));
            float e0 = expf(v0 - m), e1 = expf(v1 - m), e2 = expf(v2 - m), e3 = expf(v3 - m);
            float s = e0 + e1 + e2 + e3;
            g_coef[2] = e0 / s;   // a34
            g_coef[3] = e1 / s;   // a314
            g_coef[4] = e2 / s;   // a37
            g_coef[5] = e3 / s;   // a310
        }
        // row 6: (6,7)=w2, (6,17)=w4, (6,10)=d1
        {
            float v0 = w[2], v1 = w[4], v2 = d1;
            float m = fmaxf(fmaxf(v0, v1), v2);
            float e0 = expf(v0 - m), e1 = expf(v1 - m), e2 = expf(v2 - m);
            float s = e0 + e1 + e2;
            g_coef[6] = e0 / s;   // a67
            g_coef[7] = e1 / s;   // a617
            g_coef[8] = e2 / s;   // a610
        }
        // row 9: (9,20)=w5, (9,10)=1-w5
        {
            float v0 = w[5], v1 = 1.0f - w[5];
            float m = fmaxf(v0, v1);
            float e0 = expf(v0 - m), e1 = expf(v1 - m);
            float s = e0 + e1;
            g_coef[9]  = e0 / s;  // a920
            g_coef[10] = e1 / s;  // a910
        }
        // row 16: (16,4)=w6, (16,14)=1-w9
        {
            float v0 = w[6], v1 = 1.0f - w[9];
            float m = fmaxf(v0, v1);
            float e0 = expf(v0 - m), e1 = expf(v1 - m);
            float s = e0 + e1;
            g_coef[11] = e0 / s;  // a164
            g_coef[12] = e1 / s;  // a1614
        }
        // row 19: (19,7)=w7, (19,17)=1-w10
        {
            float v0 = w[7], v1 = 1.0f - w[10];
            float m = fmaxf(v0, v1);
            float e0 = expf(v0 - m), e1 = expf(v1 - m);
            float s = e0 + e1;
            g_coef[13] = e0 / s;  // a197
            g_coef[14] = e1 / s;  // a1917
        }
        // row 22: (22,10)=w8, (22,20)=1-w11
        {
            float v0 = w[8], v1 = 1.0f - w[11];
            float m = fmaxf(v0, v1);
            float e0 = expf(v0 - m), e1 = expf(v1 - m);
            float s = e0 + e1;
            g_coef[15] = e0 / s;  // a2210
            g_coef[16] = e1 / s;  // a2220
        }
        // pi = softmax(init_kernel)
        {
            float m = -1e30f;
            for (int i = 0; i < 24; i++) m = fmaxf(m, ik[i]);
            float e[24];
            float s = 0.0f;
            for (int i = 0; i < 24; i++) { e[i] = expf(ik[i] - m); s += e[i]; }
            for (int i = 0; i < 24; i++) g_pi[i] = e[i] / s;
        }
    }
    // Emission table: Bem[s][pp][p][c] = softmax_c(ew[s,pp,p,:]), store transposed
    // as g_Bst[ctx*20 + s] with ctx = pp*16 + p*4 + c.
    for (int idx = tid; idx < 17 * 16; idx += blockDim.x) {
        int s = idx >> 4;
        int pq = idx & 15;              // pp*4 + p
        const float* p = ew + s * 64 + pq * 4;
        float v0 = p[0], v1 = p[1], v2 = p[2], v3 = p[3];
        float m = fmaxf(fmaxf(v0, v1), fmaxf(v2, v3));
        float e0 = expf(v0 - m), e1 = expf(v1 - m), e2 = expf(v2 - m), e3 = expf(v3 - m);
        float ss = e0 + e1 + e2 + e3;
        int base = pq * 4;              // ctx for c=0
        g_Bst[(base + 0) * 20 + s] = e0 / ss;
        g_Bst[(base + 1) * 20 + s] = e1 / ss;
        g_Bst[(base + 2) * 20 + s] = e2 / ss;
        g_Bst[(base + 3) * 20 + s] = e3 / ss;
    }
}

// ---------------------------------------------------------------------------
// Forward kernel
// ---------------------------------------------------------------------------
struct Coef {
    float a00, a01, a34, a314, a37, a310, a67, a617, a610,
          a920, a910, a164, a1614, a197, a1917, a2210, a2220;
};

template <bool WITH_E>
__device__ __forceinline__ void hmm_step(const float (&s)[24], float (&d)[24],
                                         const float* __restrict__ Bsh, int ctx,
                                         const Coef& k) {
    // Sparse A^T matvec: acc[col] = sum over structural entries
    float t0  = k.a00 * s[0];
    float t1  = k.a01 * s[0];
    float t4  = fmaf(k.a34,  s[3], k.a164 * s[16]);
    float t7  = fmaf(k.a37,  s[3], fmaf(k.a67,  s[6], k.a197 * s[19]));
    float t10 = fmaf(k.a310, s[3], fmaf(k.a610, s[6], fmaf(k.a910, s[9], k.a2210 * s[22])));
    float t13 = fmaf(0.5f, s[13], s[12]);
    float t14 = fmaf(k.a314, s[3], k.a1614 * s[16]);
    float t17 = fmaf(k.a617, s[6], k.a1917 * s[19]);
    float t20 = fmaf(k.a920, s[9], k.a2220 * s[22]);
    float t23 = fmaf(0.5f, s[13], s[23]);
    if (WITH_E) {
        const float4* row = reinterpret_cast<const float4*>(Bsh + ctx * 20);
        float4 e0 = row[0], e1 = row[1], e2 = row[2], e3 = row[3];
        float e16 = Bsh[ctx * 20 + 16];
        const float SIXTH = 0.166666666666666667f;
        d[0]  = t0   * e0.x;  d[1]  = t1   * e0.y;  d[2]  = s[1]  * e0.z;  d[3]  = s[2]  * e0.w;
        d[4]  = t4   * e1.x;  d[5]  = s[4] * e1.y;  d[6]  = s[5]  * e1.z;  d[7]  = t7    * e1.w;
        d[8]  = s[7] * e2.x;  d[9]  = s[8] * e2.y;  d[10] = t10   * e2.z;  d[11] = s[10] * e2.w;
        d[12] = s[11]* e3.x;  d[13] = t13  * e3.y;  d[14] = t14   * e3.z;  d[15] = s[14] * e3.w;
        d[16] = s[15]* e16;
        d[17] = t17  * SIXTH; d[18] = s[17]* SIXTH; d[19] = s[18] * SIXTH;
        d[20] = t20  * SIXTH; d[21] = s[20]* SIXTH; d[22] = s[21] * SIXTH; d[23] = t23 * SIXTH;
    } else {
        d[0]  = t0;    d[1]  = t1;    d[2]  = s[1];  d[3]  = s[2];
        d[4]  = t4;    d[5]  = s[4];  d[6]  = s[5];  d[7]  = t7;
        d[8]  = s[7];  d[9]  = s[8];  d[10] = t10;   d[11] = s[10];
        d[12] = s[11]; d[13] = t13;   d[14] = t14;   d[15] = s[14];
        d[16] = s[15];
        d[17] = t17;   d[18] = s[17]; d[19] = s[18];
        d[20] = t20;   d[21] = s[20]; d[22] = s[21]; d[23] = t23;
    }
}

__device__ __forceinline__ float sum24(const float (&a)[24]) {
    float s01 = (a[0] + a[1])   + (a[2] + a[3]);
    float s23 = (a[4] + a[5])   + (a[6] + a[7]);
    float s45 = (a[8] + a[9])   + (a[10] + a[11]);
    float s67 = (a[12] + a[13]) + (a[14] + a[15]);
    float s89 = (a[16] + a[17]) + (a[18] + a[19]);
    float sab = (a[20] + a[21]) + (a[22] + a[23]);
    return ((s01 + s23) + (s45 + s67)) + (s89 + sab);
}

__global__ __launch_bounds__(32, 1)
void forward_kernel(const int* __restrict__ seq, float* __restrict__ out) {
    __shared__ __align__(16) float Bsh[64 * 20];
    for (int i = threadIdx.x; i < 64 * 20; i += 32) Bsh[i] = g_Bst[i];
    __syncthreads();

    Coef k;
    k.a00   = g_coef[0];  k.a01   = g_coef[1];
    k.a34   = g_coef[2];  k.a314  = g_coef[3];  k.a37  = g_coef[4];  k.a310 = g_coef[5];
    k.a67   = g_coef[6];  k.a617  = g_coef[7];  k.a610 = g_coef[8];
    k.a920  = g_coef[9];  k.a910  = g_coef[10];
    k.a164  = g_coef[11]; k.a1614 = g_coef[12];
    k.a197  = g_coef[13]; k.a1917 = g_coef[14];
    k.a2210 = g_coef[15]; k.a2220 = g_coef[16];

    int b = blockIdx.x * 32 + threadIdx.x;
    const int4* sq4 = reinterpret_cast<const int4*>(seq + b * T_LEN);

    float A[24], B[24];
    #pragma unroll
    for (int i = 0; i < 24; i++) A[i] = g_pi[i];

    // t=0 and t=1 have uniform E=1/6 (start context): contributes 2*ln(1/6),
    // residual mass absorbed by checkpoint renormalizations.
    // t=1: pure transition step (uniform E cancels up to the absorbed scale).
    hmm_step<false>(A, B, Bsh, 0, k);

    int4 v = sq4[0];
    int ctx = ((((v.x << 2) | v.y) << 2) | v.z) & 63;   // (seq0, seq1, seq2)
    hmm_step<true>(B, A, Bsh, ctx, k);                  // t=2
    ctx = ((ctx << 2) | v.w) & 63;
    hmm_step<true>(A, B, Bsh, ctx, k);                  // t=3

    float loglik = -3.58351893845611f;                  // 2 * ln(1/6)

    for (int j = 1; j < 500; ++j) {
        int4 u = sq4[j];
        ctx = ((ctx << 2) | u.x) & 63; hmm_step<true>(B, A, Bsh, ctx, k);
        ctx = ((ctx << 2) | u.y) & 63; hmm_step<true>(A, B, Bsh, ctx, k);
        ctx = ((ctx << 2) | u.z) & 63; hmm_step<true>(B, A, Bsh, ctx, k);
        ctx = ((ctx << 2) | u.w) & 63; hmm_step<true>(A, B, Bsh, ctx, k);
        if ((j & 3) == 3) {
            float S = sum24(B);
            loglik += logf(S);
            float inv = 1.0f / S;
            #pragma unroll
            for (int i = 0; i < 24; i++) B[i] *= inv;
        }
    }
    out[b] = loglik;
}

// ---------------------------------------------------------------------------
// Launch
// ---------------------------------------------------------------------------
extern "C" void kernel_launch(void* const* d_in, const int* in_sizes, int n_in,
                              void* d_out, int out_size) {
    const float* transition_kernel = (const float*)d_in[0];
    const float* emission_kernel   = (const float*)d_in[1];
    const float* init_kernel       = (const float*)d_in[2];
    const int*   seq               = (const int*)d_in[3];
    float* out = (float*)d_out;

    setup_kernel<<<1, 256>>>(transition_kernel, emission_kernel, init_kernel);
    forward_kernel<<<BATCH / 32, 32>>>(seq, out);
}